// round 15
// baseline (speedup 1.0000x reference)
#include <cuda_runtime.h>
#include <cuda_fp16.h>
#include <cstdint>

#define BATCH 32
#define T_LEN 2048
#define S_DIM 512
#define E_DIM 32
#define SLICES 4              // CTAs per batch (cluster size)
#define ROWS 128              // A-rows owned per CTA (K slice)
#define NTHREADS 512
#define TARGET_EXP 6
#define FIXP 4194304.0f       // 2^22 partial fixed-point scale
#define FIXP_INV (1.0f / 4194304.0f)
#define ZFIX 16384.0f         // 2^14 z fixed point
#define ZFIX_INV (1.0f / 16384.0f)
#define VBYTES (S_DIM * 4)    // 512 red.async x 4B per consumer per step
#define ZFBYTES (SLICES * 16 * 4)

__device__ int g_obs[BATCH * T_LEN];

__global__ void obs_extract_kernel(const float* __restrict__ inputs) {
    int idx = blockIdx.x * blockDim.x + threadIdx.x;
    if (idx >= BATCH * T_LEN) return;
    const float* p = inputs + (size_t)idx * E_DIM;
    int e = 0;
#pragma unroll
    for (int i = 0; i < E_DIM; i++) {
        if (p[i] > 0.5f) e = i;
    }
    g_obs[idx] = e;
}

__device__ __forceinline__ uint32_t smem_u32(const void* p) {
    uint32_t a;
    asm("{ .reg .u64 t; cvta.to.shared.u64 t, %1; cvt.u32.u64 %0, t; }"
        : "=r"(a) : "l"(p));
    return a;
}

__device__ __forceinline__ uint32_t mapa_u32(uint32_t saddr, uint32_t rank) {
    uint32_t ra;
    asm("mapa.shared::cluster.u32 %0, %1, %2;" : "=r"(ra) : "r"(saddr), "r"(rank));
    return ra;
}

__device__ __forceinline__ void cluster_sync_() {
    asm volatile("barrier.cluster.arrive.aligned;" ::: "memory");
    asm volatile("barrier.cluster.wait.aligned;" ::: "memory");
}

// tx-counted async store (4B) into (remote) cluster smem
__device__ __forceinline__ void st_async_u32(uint32_t raddr, uint32_t v, uint32_t rmbar) {
    asm volatile(
        "st.async.shared::cluster.mbarrier::complete_tx::bytes.b32 [%0], %1, [%2];"
        :: "r"(raddr), "r"(v), "r"(rmbar) : "memory");
}

// tx-counted async ADD (u32) into (remote) cluster smem — the network does the reduce
__device__ __forceinline__ void red_async_add_u32(uint32_t raddr, uint32_t v, uint32_t rmbar) {
    asm volatile(
        "red.async.relaxed.cluster.shared::cluster.mbarrier::complete_tx::bytes.add.u32 [%0], %1, [%2];"
        :: "r"(raddr), "r"(v), "r"(rmbar) : "memory");
}

// untracked remote atomic add (lagged-Z ring, consumed >=1 full step later)
__device__ __forceinline__ void red_relaxed_add_u32(uint32_t raddr, uint32_t v) {
    asm volatile("red.relaxed.cluster.shared::cluster.add.u32 [%0], %1;"
                 :: "r"(raddr), "r"(v) : "memory");
}

__device__ __forceinline__ void mbar_init(uint32_t mbar, uint32_t cnt) {
    asm volatile("mbarrier.init.shared.b64 [%0], %1;" :: "r"(mbar), "r"(cnt) : "memory");
}

__device__ __forceinline__ void mbar_expect_tx(uint32_t mbar, uint32_t bytes) {
    asm volatile("mbarrier.arrive.expect_tx.shared.b64 _, [%0], %1;"
                 :: "r"(mbar), "r"(bytes) : "memory");
}

__device__ __forceinline__ void mbar_wait_parity(uint32_t mbar, uint32_t parity) {
    asm volatile(
        "{\n\t"
        ".reg .pred P;\n\t"
        "WAIT_%=: \n\t"
        "mbarrier.try_wait.parity.acquire.cluster.shared::cta.b64 P, [%0], %1, 0x989680;\n\t"
        "@!P bra WAIT_%=;\n\t"
        "}"
        :: "r"(mbar), "r"(parity) : "memory");
}

__device__ __forceinline__ float warp_sum32(float v) {
#pragma unroll
    for (int o = 16; o > 0; o >>= 1)
        v += __shfl_xor_sync(0xffffffffu, v, o);
    return v;
}

__global__ void __cluster_dims__(SLICES, 1, 1) __launch_bounds__(NTHREADS, 1)
hmm_forward_kernel(const float* __restrict__ A,
                   const float* __restrict__ Bem,
                   const float* __restrict__ pi,
                   float* __restrict__ out)
{
    __shared__ __align__(16) uint32_t alpha_s[ROWS / 2];   // 64 half2 (own rows)
    __shared__ __align__(16) uint32_t accbuf[2][ROWS];     // fixed-point partial sums
    __shared__ __align__(16) uint32_t zrem[4];             // fixed-point Z ring
    __shared__ __align__(16) float    zfin[SLICES * 16];   // exact final z partials
    __shared__ __half  bem_h[E_DIM][S_DIM];                // full emission table fp16
    __shared__ float   embias[E_DIM];
    __shared__ int     obs_s[T_LEN];
    __shared__ __align__(8) unsigned long long mbar_store[3]; // v0, v1, zfin

    const int tid = threadIdx.x;
    const int w = tid >> 5;
    const int l = tid & 31;
    const int j = tid;              // global output column owned by this thread
    uint32_t crank;
    asm("mov.u32 %0, %%cluster_ctarank;" : "=r"(crank));
    const int c = (int)crank;
    const int b = blockIdx.x / SLICES;

    // ---- A slice: rows [128c, 128c+128), column j, as 64 fp16x2 regs ----
    __half2 a2[64];
#pragma unroll
    for (int p = 0; p < 64; p++) {
        float r0 = A[(size_t)(ROWS * c + 2 * p) * S_DIM + j];
        float r1 = A[(size_t)(ROWS * c + 2 * p + 1) * S_DIM + j];
        a2[p] = __floats2half2_rn(r0, r1);
    }

    // full emission table (fp16), needed because producers apply em for all columns
    for (int i = tid; i < E_DIM * S_DIM; i += NTHREADS) {
        int e = i >> 9, jj = i & 511;
        bem_h[e][jj] = __float2half(Bem[(size_t)jj * E_DIM + e]);
    }
    for (int i = tid; i < T_LEN; i += NTHREADS) obs_s[i] = g_obs[b * T_LEN + i];
    if (tid < 4) zrem[tid] = 0u;
    if (tid >= 8 && tid < 8 + 2 * ROWS)
        accbuf[0][tid - 8] = 0u;   // zero both buffers (256 words)

    // ---- per-symbol mean emission (lagged scale estimate) ----
    {
        int e = tid >> 4, seg = tid & 15;
        float s = 0.0f;
#pragma unroll 4
        for (int i = 0; i < 32; i++)
            s += Bem[(size_t)(seg * 32 + i) * E_DIM + e];
#pragma unroll
        for (int o = 8; o > 0; o >>= 1)
            s += __shfl_xor_sync(0xffffffffu, s, o);
        if (seg == 0) embias[e] = s * (1.0f / 512.0f);
    }

    const uint32_t acc_sa  = smem_u32(&accbuf[0][0]);
    const uint32_t z_sa    = smem_u32(&zrem[0]);
    const uint32_t zf_sa   = smem_u32(&zfin[0]);
    const uint32_t mbar_sa = smem_u32(&mbar_store[0]);
    // mbar: v[buf] = buf*8 ; zfin = 16

    if (tid == 0) {
#pragma unroll
        for (int i = 0; i < 3; i++) mbar_init(mbar_sa + i * 8, 1);
        mbar_expect_tx(mbar_sa + 16, ZFBYTES);
    }
    __syncthreads();
    cluster_sync_();   // peers' mbarriers + zeroed buffers visible

    // hoisted remote addresses (scalars)
    const uint32_t my_acc_r = mapa_u32(acc_sa, (uint32_t)(j >> 7)) + (uint32_t)((j & 127) * 4);
    const uint32_t my_mb_r  = mapa_u32(mbar_sa, (uint32_t)(j >> 7));
    const uint32_t zr_l  = mapa_u32(z_sa, (uint32_t)(l & 3));
    const uint32_t zf_l  = mapa_u32(zf_sa, (uint32_t)(l & 3));
    const uint32_t mbzf_l = mapa_u32(mbar_sa, (uint32_t)(l & 3)) + 16;

    // ---- PROLOGUE: w_0 for OWN rows directly into alpha_s; z(0) -> ring slot 0 ----
    if (tid < 64) {
        const int e0 = obs_s[0];
        int g0 = ROWS * c + 2 * tid;
        float m0 = pi[g0]     * __half2float(bem_h[e0][g0])     * 64.0f;
        float m1 = pi[g0 + 1] * __half2float(bem_h[e0][g0 + 1]) * 64.0f;
        __half2 h = __floats2half2_rn(m0, m1);
        alpha_s[tid] = *reinterpret_cast<uint32_t*>(&h);
        float z = warp_sum32(m0 + m1);
        if (l < 4) red_relaxed_add_u32(zr_l, (uint32_t)__float2uint_rn(z * ZFIX));
    }

    int K = TARGET_EXP;
    int d_prev = 0;

    for (int t = 0; t < T_LEN - 1; t++) {
        const int buf = t & 1;
        const int nbuf = buf ^ 1;

        // ---- scale (all threads, deterministic & cluster-uniform; lagged Z) ----
        const int en = obs_s[t + 1];
        float Zm;
        int dp;
        if (t == 0) {
            Zm = 64.0f * embias[obs_s[0]] * embias[en];
            dp = 0;
        } else {
            uint32_t zu = *(volatile uint32_t*)&zrem[(t - 1) & 3];
            Zm = (float)zu * ZFIX_INV * embias[obs_s[t]] * embias[en];
            dp = d_prev;
        }
        int ex = ((__float_as_int(Zm) >> 23) & 255) - 127;
        int d = TARGET_EXP - ex - dp;
        d = d < -48 ? -48 : (d > 48 ? 48 : d);
        float scale = __int_as_float((uint32_t)(d + 127) << 23);
        d_prev = d;
        K += d;

        // ---- consumer epilogue: assemble own alpha rows from reduced partials ----
        if (t > 0) {
            const uint32_t par = (uint32_t)(((t >> 1) + 1 - buf) & 1);
            if (tid == 0) mbar_expect_tx(mbar_sa + buf * 8, VBYTES);
            if (tid < 64) {
                mbar_wait_parity(mbar_sa + buf * 8, par);
                uint2 pq = *reinterpret_cast<uint2*>(&accbuf[buf][2 * tid]);
                *reinterpret_cast<uint2*>(&accbuf[buf][2 * tid]) = make_uint2(0u, 0u);
                float f0 = (float)pq.x * FIXP_INV;
                float f1 = (float)pq.y * FIXP_INV;
                __half2 h = __floats2half2_rn(f0, f1);
                alpha_s[tid] = *reinterpret_cast<uint32_t*>(&h);
            }
        }
        __syncthreads();
        if (tid == 256) *(volatile uint32_t*)&zrem[(t + 2) & 3] = 0u;

        // ---- matvec: own 128 rows x column j (broadcast LDS, 64 HFMA2) ----
        __half2 acc0 = __float2half2_rn(0.0f);
        __half2 acc1 = acc0;
        const uint4* ab = reinterpret_cast<const uint4*>(&alpha_s[0]);
#pragma unroll
        for (int q = 0; q < 16; q++) {
            uint4 av = ab[q];
            acc0 = __hfma2(*reinterpret_cast<__half2*>(&av.x), a2[4 * q + 0], acc0);
            acc1 = __hfma2(*reinterpret_cast<__half2*>(&av.y), a2[4 * q + 1], acc1);
            acc0 = __hfma2(*reinterpret_cast<__half2*>(&av.z), a2[4 * q + 2], acc0);
            acc1 = __hfma2(*reinterpret_cast<__half2*>(&av.w), a2[4 * q + 3], acc1);
        }
        acc0 = __hadd2(acc0, acc1);
        float2 f0 = __half22float2(acc0);
        float sum = f0.x + f0.y;

        // ---- producer tail: apply em*scale, ship fixed-point partial via red.async ----
        float m = sum * __half2float(bem_h[en][j]) * scale;
        uint32_t u = __float2uint_rn(m * FIXP);
        red_async_add_u32(my_acc_r + (uint32_t)(nbuf * ROWS * 4), u,
                          my_mb_r + (uint32_t)(nbuf * 8));

        // ---- z-partial of shipped values (off critical path) ----
        float z = warp_sum32(m);
        if (l < 4) {
            red_relaxed_add_u32(zr_l + (uint32_t)(((t + 1) & 3) * 4),
                                (uint32_t)__float2uint_rn(z * ZFIX));
            if (t == T_LEN - 2)
                st_async_u32(zf_l + (uint32_t)((c * 16 + w) * 4),
                             __float_as_uint(z), mbzf_l);
        }
    }

    // ---- FINAL: exact Z(T-1) ----
    mbar_wait_parity(mbar_sa + 16, 0);
    if (c == 0 && tid == 0) {
        float Z = 0.0f;
#pragma unroll
        for (int i = 0; i < SLICES * 16; i++) Z += zfin[i];
        out[b] = (log2f(Z) - (float)K) * 0.6931471805599453f;
    }
    cluster_sync_();   // no CTA exits while peers may still target its smem
}

extern "C" void kernel_launch(void* const* d_in, const int* in_sizes, int n_in,
                              void* d_out, int out_size)
{
    const float* inputs = (const float*)d_in[0];  // [B,T,E] one-hot
    const float* A      = (const float*)d_in[1];  // [S,S]
    const float* Bem    = (const float*)d_in[2];  // [S,E]
    const float* pi     = (const float*)d_in[3];  // [S]
    float* out = (float*)d_out;                   // [B]

    obs_extract_kernel<<<(BATCH * T_LEN + 255) / 256, 256>>>(inputs);
    hmm_forward_kernel<<<BATCH * SLICES, NTHREADS>>>(A, Bem, pi, out);
}